// round 4
// baseline (speedup 1.0000x reference)
#include <cuda_runtime.h>

// ---------------------------------------------------------------------------
// SNN: LAYERS [2048,2048,2048,512], B=32, T=100, LIF with tau_syn=5, tau_mem=20
//
// Restructured: per-layer big GEMM over all T (M=3200,K=2048) followed by an
// elementwise LIF scan over time. GEMM uses packed fp32x2 FMA (fma.rn.f32x2).
// ---------------------------------------------------------------------------

#define TT   100
#define BB   32
#define NIN  2048
#define NH   2048
#define NOUT 512
#define MM   (TT * BB)            // 3200

// scratch (allocation-free: __device__ globals)
__device__ __align__(16) float g_S_in[TT * BB * NIN];   // input spikes / layer1 spikes (reused)
__device__ __align__(16) float g_S_a [TT * BB * NH];    // layer0 spikes
__device__ __align__(16) float g_I   [TT * BB * NH];    // current buffer (reused per layer)
__device__ unsigned int g_count;

// ---------------------------------------------------------------------------
// 1) Poisson encode: spikes_in[t,b,i] = noise[t,b,i] < clip(x[b,i],0,1)
// ---------------------------------------------------------------------------
__global__ void encode_kernel(const float* __restrict__ x,
                              const float* __restrict__ noise)
{
    if (blockIdx.x == 0 && threadIdx.x == 0) g_count = 0u;
    int idx = blockIdx.x * blockDim.x + threadIdx.x;
    if (idx < TT * BB * NIN) {
        int bi = idx % (BB * NIN);
        float r = x[bi];
        r = fminf(fmaxf(r, 0.0f), 1.0f);
        g_S_in[idx] = (noise[idx] < r) ? 1.0f : 0.0f;
    }
}

// ---------------------------------------------------------------------------
// 2) GEMM (NT): C[m,n] = sum_k A[m,k] * W[n,k]
//    M=3200 (always), K=2048, N in {2048, 512}. All dims divide the tiles.
//    Block tile 128x128, K-tile 16, 256 threads, 8x8 micro-tile per thread,
//    accumulators packed as f32x2 (2 N-columns per 64-bit register).
// ---------------------------------------------------------------------------
#define BM 128
#define BN 128
#define BK 16

__global__ __launch_bounds__(256, 2)
void gemm_nt_kernel(const float* __restrict__ A, const float* __restrict__ W,
                    float* __restrict__ C, int K, int N)
{
    __shared__ __align__(16) float As[BK][BM];
    __shared__ __align__(16) float Bs[BK][BN];

    const int tid = threadIdx.x;
    const int tx  = tid & 15;     // 16 column-groups of 8
    const int ty  = tid >> 4;     // 16 row-groups of 8
    const int m0  = blockIdx.y * BM;
    const int n0  = blockIdx.x * BN;

    unsigned long long acc[8][4];
#pragma unroll
    for (int i = 0; i < 8; i++)
#pragma unroll
        for (int j = 0; j < 4; j++) acc[i][j] = 0ull;

    const float* Abase = A + (size_t)m0 * K;
    const float* Wbase = W + (size_t)n0 * K;

    for (int kt = 0; kt < K; kt += BK) {
        // --- load 128x16 tiles of A and W (K-contiguous), store k-major ---
#pragma unroll
        for (int v = 0; v < 2; v++) {
            int lin = tid + v * 256;          // 0..511
            int row = lin >> 2;               // 0..127
            int kq  = (lin & 3) << 2;         // 0,4,8,12
            float4 av = *(const float4*)(Abase + (size_t)row * K + kt + kq);
            As[kq + 0][row] = av.x;
            As[kq + 1][row] = av.y;
            As[kq + 2][row] = av.z;
            As[kq + 3][row] = av.w;
            float4 wv = *(const float4*)(Wbase + (size_t)row * K + kt + kq);
            Bs[kq + 0][row] = wv.x;
            Bs[kq + 1][row] = wv.y;
            Bs[kq + 2][row] = wv.z;
            Bs[kq + 3][row] = wv.w;
        }
        __syncthreads();

#pragma unroll
        for (int k = 0; k < BK; k++) {
            float4 a0 = *(const float4*)&As[k][ty * 8];
            float4 a1 = *(const float4*)&As[k][ty * 8 + 4];
            const unsigned long long* bp =
                (const unsigned long long*)&Bs[k][tx * 8];
            unsigned long long b[4];
            b[0] = bp[0]; b[1] = bp[1]; b[2] = bp[2]; b[3] = bp[3];
            float am[8] = {a0.x, a0.y, a0.z, a0.w, a1.x, a1.y, a1.z, a1.w};
#pragma unroll
            for (int i = 0; i < 8; i++) {
                unsigned long long a2;
                asm("mov.b64 %0, {%1, %1};" : "=l"(a2) : "f"(am[i]));
#pragma unroll
                for (int j = 0; j < 4; j++)
                    asm("fma.rn.f32x2 %0, %1, %2, %0;"
                        : "+l"(acc[i][j]) : "l"(a2), "l"(b[j]));
            }
        }
        __syncthreads();
    }

    // --- store (packed 8-byte stores; low lane = lower column) ---
#pragma unroll
    for (int i = 0; i < 8; i++) {
        float* crow = C + (size_t)(m0 + ty * 8 + i) * N + n0 + tx * 8;
#pragma unroll
        for (int j = 0; j < 4; j++)
            *(unsigned long long*)(crow + 2 * j) = acc[i][j];
    }
}

// ---------------------------------------------------------------------------
// 3) LIF scan over time for one layer (hidden layers: writes spike train)
//    syn' = syn + (I - syn/5) ; mem' = mem + (syn' - mem/20)
//    spike = mem' >= 1 ; mem -> 0 on spike ; clamp mem >= 0
// ---------------------------------------------------------------------------
__global__ void lif_scan_kernel(const float* __restrict__ I,
                                const float* __restrict__ bias,
                                float* __restrict__ Sout, int N)
{
    const int idx = blockIdx.x * blockDim.x + threadIdx.x;   // b*N + j
    const int j = idx & (N - 1);
    const float bj = bias[j];
    const int stride = BB * N;

    float syn = 0.0f, mem = 0.0f;
    int cnt = 0;
#pragma unroll 4
    for (int t = 0; t < TT; t++) {
        float Iv = I[(size_t)t * stride + idx] + bj;
        syn = syn + (Iv - syn * (1.0f / 5.0f));
        mem = mem + (syn - mem * (1.0f / 20.0f));
        float sp;
        if (mem >= 1.0f) { sp = 1.0f; mem = 0.0f; cnt++; }
        else             { sp = 0.0f; if (mem < 0.0f) mem = 0.0f; }
        Sout[(size_t)t * stride + idx] = sp;
    }
    unsigned s = __reduce_add_sync(0xFFFFFFFFu, (unsigned)cnt);
    if ((threadIdx.x & 31) == 0) atomicAdd(&g_count, s);
}

// Output layer scan: accumulates time-mean spikes directly into d_out.
__global__ void lif_scan_out_kernel(const float* __restrict__ I,
                                    const float* __restrict__ bias,
                                    float* __restrict__ out)
{
    const int idx = blockIdx.x * blockDim.x + threadIdx.x;   // b*512 + j
    const int j = idx & (NOUT - 1);
    const float bj = bias[j];
    const int stride = BB * NOUT;

    float syn = 0.0f, mem = 0.0f;
    int cnt = 0;
#pragma unroll 4
    for (int t = 0; t < TT; t++) {
        float Iv = I[(size_t)t * stride + idx] + bj;
        syn = syn + (Iv - syn * (1.0f / 5.0f));
        mem = mem + (syn - mem * (1.0f / 20.0f));
        if (mem >= 1.0f) { mem = 0.0f; cnt++; }
        else if (mem < 0.0f) mem = 0.0f;
    }
    out[idx] = (float)cnt * (1.0f / (float)TT);
    unsigned s = __reduce_add_sync(0xFFFFFFFFu, (unsigned)cnt);
    if ((threadIdx.x & 31) == 0) atomicAdd(&g_count, s);
}

__global__ void finalize_kernel(float* __restrict__ out, int pos)
{
    out[pos] = (float)g_count;
}

// ---------------------------------------------------------------------------
// kernel_launch
// ---------------------------------------------------------------------------
extern "C" void kernel_launch(void* const* d_in, const int* in_sizes, int n_in,
                              void* d_out, int out_size)
{
    const float *x = nullptr, *noise = nullptr;
    const float *W0 = nullptr, *b0 = nullptr, *W1 = nullptr, *b1 = nullptr;
    const float *W2 = nullptr, *b2 = nullptr;

    // identify inputs by element count (robust to metadata ordering)
    for (int i = 0; i < n_in; i++) {
        long s = (long)in_sizes[i];
        const float* p = (const float*)d_in[i];
        if      (s == (long)BB * NIN)            x = p;
        else if (s == (long)TT * BB * NIN)       noise = p;
        else if (s == (long)NH * NIN)            { if (!W0) W0 = p; else W1 = p; }
        else if (s == (long)NH)                  { if (!b0) b0 = p; else b1 = p; }
        else if (s == (long)NOUT * NH)           W2 = p;
        else if (s == (long)NOUT)                b2 = p;
        // s == 1 -> time_steps (compile-time constant TT)
    }

    void *pSin, *pSa, *pI;
    cudaGetSymbolAddress(&pSin, g_S_in);
    cudaGetSymbolAddress(&pSa,  g_S_a);
    cudaGetSymbolAddress(&pI,   g_I);
    float* Sin  = (float*)pSin;
    float* Sa   = (float*)pSa;
    float* Ibuf = (float*)pI;
    float* out  = (float*)d_out;

    // 1) encode input spikes (also zeroes the spike counter)
    encode_kernel<<<(TT * BB * NIN + 255) / 256, 256>>>(x, noise);

    // 2) layer 0: GEMM over all timesteps, then LIF scan
    gemm_nt_kernel<<<dim3(NH / BN, MM / BM), 256>>>(Sin, W0, Ibuf, NIN, NH);
    lif_scan_kernel<<<(BB * NH) / 256, 256>>>(Ibuf, b0, Sa, NH);

    // 3) layer 1 (reuse Sin as the layer-1 spike buffer)
    gemm_nt_kernel<<<dim3(NH / BN, MM / BM), 256>>>(Sa, W1, Ibuf, NH, NH);
    lif_scan_kernel<<<(BB * NH) / 256, 256>>>(Ibuf, b1, Sin, NH);

    // 4) layer 2 (output): GEMM, then scan that writes time-mean directly
    gemm_nt_kernel<<<dim3(NOUT / BN, MM / BM), 256>>>(Sin, W2, Ibuf, NH, NOUT);
    lif_scan_out_kernel<<<(BB * NOUT) / 256, 256>>>(Ibuf, b2, out);

    // 5) total spike count scalar
    finalize_kernel<<<1, 1>>>(out, out_size - 1);
}